// round 4
// baseline (speedup 1.0000x reference)
#include <cuda_runtime.h>
#include <math.h>

// Problem constants
#define BATCH 8
#define NNODES 4096
#define DIN0 64
#define DHID 128
#define DOUT0 64
#define CAP 512          // max neighbors per row (mean ~82 at 2% density; P(>512)~0)

// ---------------- static device scratch (no allocations allowed) -------------
// d_h1 is reused: layer-1 linear output (B*N*128 floats), then layer-2 linear
// output (B*N*64 floats) — lifetimes are disjoint.
__device__ int   d_col[NNODES * CAP];            // 8 MB
__device__ int   d_deg[NNODES];
__device__ float d_h1[BATCH * NNODES * DHID];    // 16 MB (aliased for h2)
__device__ float d_t1[BATCH * NNODES * DHID];    // 16 MB
__device__ float d_wt1[DIN0 * DHID];             // W1^T  [k][c]
__device__ float d_wt2[DHID * DOUT0];            // W2^T  [k][c]

// ---------------- transpose W1, W2 into k-major layout -----------------------
__global__ void prep_kernel(const float* __restrict__ W1, const float* __restrict__ W2) {
    int i = blockIdx.x * blockDim.x + threadIdx.x;
    if (i < DHID * DIN0) {            // W1: [128][64] -> wt1[k*128 + c]
        int c = i / DIN0, k = i % DIN0;
        d_wt1[k * DHID + c] = W1[i];
    }
    if (i < DOUT0 * DHID) {           // W2: [64][128] -> wt2[k*64 + c]
        int c = i / DHID, k = i % DHID;
        d_wt2[k * DOUT0 + c] = W2[i];
    }
}

// ---------------- build CSR from dense binary graph (order-preserving) -------
__global__ void build_csr_kernel(const float* __restrict__ graph) {
    int row  = blockIdx.x * (blockDim.x >> 5) + (threadIdx.x >> 5);
    int lane = threadIdx.x & 31;
    if (row >= NNODES) return;
    const float* g = graph + (size_t)row * NNODES;
    int cnt = 0;
    for (int base = 0; base < NNODES; base += 32) {
        float v = g[base + lane];
        unsigned ball = __ballot_sync(0xffffffffu, v != 0.0f);
        int prefix = __popc(ball & ((1u << lane) - 1u));
        if (v != 0.0f) {
            int pos = cnt + prefix;
            if (pos < CAP) d_col[row * CAP + pos] = base + lane;
        }
        cnt += __popc(ball);
    }
    if (lane == 0) d_deg[row] = (cnt < CAP) ? cnt : CAP;
}

// ---------------- linear body: out[r][c] = sum_k x[r][k] * Wt[k][c] ----------
template <int DIN, int DOUT>
__device__ __forceinline__ void lin_body(const float* __restrict__ x,
                                         const float* __restrict__ wt,
                                         float* __restrict__ out) {
    constexpr int RPB = 32;
    __shared__ float xs[RPB * DIN];
    long base = (long)blockIdx.x * RPB;
    const float4* xg  = (const float4*)(x + base * DIN);
    float4*       xs4 = (float4*)xs;
    for (int i = threadIdx.x; i < RPB * DIN / 4; i += blockDim.x) xs4[i] = xg[i];
    __syncthreads();

    int c = threadIdx.x;   // blockDim == DOUT
    float acc[RPB];
#pragma unroll
    for (int r = 0; r < RPB; r++) acc[r] = 0.0f;

    for (int k = 0; k < DIN; k += 4) {
        float w0 = wt[(k + 0) * DOUT + c];
        float w1 = wt[(k + 1) * DOUT + c];
        float w2 = wt[(k + 2) * DOUT + c];
        float w3 = wt[(k + 3) * DOUT + c];
#pragma unroll
        for (int r = 0; r < RPB; r++) {
            float4 xv = *(const float4*)&xs[r * DIN + k];
            acc[r] = fmaf(xv.x, w0, fmaf(xv.y, w1, fmaf(xv.z, w2, fmaf(xv.w, w3, acc[r]))));
        }
    }
#pragma unroll
    for (int r = 0; r < RPB; r++) out[(base + r) * DOUT + c] = acc[r];
}

__global__ void lin1_kernel(const float* __restrict__ x) {
    lin_body<DIN0, DHID>(x, d_wt1, d_h1);
}
__global__ void lin2_kernel() {
    lin_body<DHID, DOUT0>(d_t1, d_wt2, d_h1);   // h2 aliases d_h1
}

// ---------------- sparse GAT aggregation: warp per (b, n) row ----------------
// out[b,n,:] = softmax_m( h[b,n]·h[b,m] over CSR neighbors ) @ h[b,m] + bias
template <int D, bool RELU>
__device__ __forceinline__ void agg_body(const float* __restrict__ h,
                                         const float* __restrict__ bias,
                                         float* __restrict__ out) {
    constexpr int VEC = D / 32;
    int warp = threadIdx.x >> 5;
    int lane = threadIdx.x & 31;
    long row = (long)blockIdx.x * (blockDim.x >> 5) + warp;   // row in [0, B*N)
    if (row >= (long)BATCH * NNODES) return;
    int n = (int)(row & (NNODES - 1));
    const float* hb = h + (size_t)(row - n) * D;   // batch base

    float f[VEC];
    if (VEC == 4) {
        float4 t = *(const float4*)(hb + (size_t)n * D + lane * 4);
        f[0] = t.x; f[1] = t.y; f[2] = t.z; f[3] = t.w;
    } else {
        float2 t = *(const float2*)(hb + (size_t)n * D + lane * 2);
        f[0] = t.x; f[1] = t.y;
    }

    float M = -INFINITY, Z = 0.0f;
    float acc[VEC];
#pragma unroll
    for (int v = 0; v < VEC; v++) acc[v] = 0.0f;

    int deg = d_deg[n];
    const int* cols = d_col + (size_t)n * CAP;

#pragma unroll 2
    for (int i = 0; i < deg; i++) {
        int m = cols[i];
        float g[VEC];
        if (VEC == 4) {
            float4 t = *(const float4*)(hb + (size_t)m * D + lane * 4);
            g[0] = t.x; g[1] = t.y; g[2] = t.z; g[3] = t.w;
        } else {
            float2 t = *(const float2*)(hb + (size_t)m * D + lane * 2);
            g[0] = t.x; g[1] = t.y;
        }
        float dot = 0.0f;
#pragma unroll
        for (int v = 0; v < VEC; v++) dot = fmaf(f[v], g[v], dot);
#pragma unroll
        for (int o = 16; o > 0; o >>= 1) dot += __shfl_xor_sync(0xffffffffu, dot, o);

        float newM = fmaxf(M, dot);
        float sc = __expf(M - newM);       // first iter: exp(-inf) = 0
        float w  = __expf(dot - newM);
        Z = Z * sc + w;
#pragma unroll
        for (int v = 0; v < VEC; v++) acc[v] = acc[v] * sc + w * g[v];
        M = newM;
    }

    float inv = 1.0f / fmaxf(Z, 1e-30f);   // deg>=1 via self-loop; guard anyway
    float* op = out + (size_t)row * D + lane * VEC;
#pragma unroll
    for (int v = 0; v < VEC; v++) {
        float o = acc[v] * inv + bias[lane * VEC + v];
        if (RELU) o = fmaxf(o, 0.0f);
        op[v] = o;
    }
}

__global__ void agg1_kernel(const float* __restrict__ b1) {
    agg_body<DHID, true>(d_h1, b1, d_t1);
}
__global__ void agg2_kernel(const float* __restrict__ b2, float* __restrict__ out) {
    agg_body<DOUT0, false>(d_h1, b2, out);      // h2 aliases d_h1
}

// ---------------- launch ------------------------------------------------------
extern "C" void kernel_launch(void* const* d_in, const int* in_sizes, int n_in,
                              void* d_out, int out_size) {
    const float* flow_x = (const float*)d_in[0];   // [B,N,64]
    const float* graph  = (const float*)d_in[1];   // [N,N]
    const float* W1     = (const float*)d_in[2];   // [128,64]
    const float* b1     = (const float*)d_in[3];   // [128]
    const float* W2     = (const float*)d_in[4];   // [64,128]
    const float* b2     = (const float*)d_in[5];   // [64]
    float*       outp   = (float*)d_out;           // [B,N,1,64]

    // 1) transpose weights
    prep_kernel<<<(DHID * DIN0 + 255) / 256, 256>>>(W1, W2);
    // 2) build CSR (shared by both layers & all batches)
    build_csr_kernel<<<NNODES / 8, 256>>>(graph);
    // 3) layer-1 linear: h1 = x @ W1^T
    lin1_kernel<<<BATCH * NNODES / 32, DHID>>>(flow_x);
    // 4) layer-1 sparse attention + bias + relu
    agg1_kernel<<<(BATCH * NNODES) / 8, 256>>>(b1);
    // 5) layer-2 linear: h2 = t1 @ W2^T  (h2 aliases d_h1)
    lin2_kernel<<<BATCH * NNODES / 32, DOUT0>>>();
    // 6) layer-2 sparse attention + bias -> final output
    agg2_kernel<<<(BATCH * NNODES) / 8, 256>>>(b2, outp);
}

// round 7
// speedup vs baseline: 1.3525x; 1.3525x over previous
#include <cuda_runtime.h>
#include <math.h>

// Problem constants
#define BATCH 8
#define NNODES 4096
#define DIN0 64
#define DHID 128
#define DOUT0 64
#define CAP 512          // max neighbors per row (mean ~82 at 2% density; P(>512)~0)

// ---------------- static device scratch (no allocations allowed) -------------
__device__ int   d_col[NNODES * CAP];            // 8 MB
__device__ int   d_deg[NNODES];
__device__ float d_h1[BATCH * NNODES * DHID];    // 16 MB (aliased for h2)
__device__ float d_t1[BATCH * NNODES * DHID];    // 16 MB
__device__ float d_wt1[DIN0 * DHID];             // W1^T  [k][c]
__device__ float d_wt2[DHID * DOUT0];            // W2^T  [k][c]

// ---------------- single-value warp sum (tail path) ---------------------------
__device__ __forceinline__ float warp_sum(float v) {
#pragma unroll
    for (int o = 16; o > 0; o >>= 1) v += __shfl_xor_sync(0xffffffffu, v, o);
    return v;
}

// ---------------- merged 4-way warp sum: 10 SHFLs for 4 reductions ------------
// After merges, lanes 0-7 hold d0 partials, 8-15 d2, 16-23 d1, 24-31 d3.
__device__ __forceinline__ void warp_sum4(float p0, float p1, float p2, float p3,
                                          float& d0, float& d1, float& d2, float& d3) {
    const unsigned FULL = 0xffffffffu;
    int lane = threadIdx.x & 31;
    // merge p0/p1 across halves (xor 16)
    float sA = (lane & 16) ? p1 : p0;
    float tA = (lane & 16) ? p0 : p1;
    sA += __shfl_xor_sync(FULL, tA, 16);
    // merge p2/p3 across halves (xor 16)
    float sB = (lane & 16) ? p3 : p2;
    float tB = (lane & 16) ? p2 : p3;
    sB += __shfl_xor_sync(FULL, tB, 16);
    // merge A/B across octets (xor 8)
    float s = (lane & 8) ? sB : sA;
    float t = (lane & 8) ? sA : sB;
    s += __shfl_xor_sync(FULL, t, 8);
    // butterfly within 8-lane groups
    s += __shfl_xor_sync(FULL, s, 4);
    s += __shfl_xor_sync(FULL, s, 2);
    s += __shfl_xor_sync(FULL, s, 1);
    // broadcast each group's result to all lanes
    d0 = __shfl_sync(FULL, s, 0);
    d2 = __shfl_sync(FULL, s, 8);
    d1 = __shfl_sync(FULL, s, 16);
    d3 = __shfl_sync(FULL, s, 24);
}

// ---------------- transpose W1, W2 into k-major layout -----------------------
__global__ void prep_kernel(const float* __restrict__ W1, const float* __restrict__ W2) {
    int i = blockIdx.x * blockDim.x + threadIdx.x;
    if (i < DHID * DIN0) {            // W1: [128][64] -> wt1[k*128 + c]
        int c = i / DIN0, k = i % DIN0;
        d_wt1[k * DHID + c] = W1[i];
    }
    if (i < DOUT0 * DHID) {           // W2: [64][128] -> wt2[k*64 + c]
        int c = i / DHID, k = i % DHID;
        d_wt2[k * DOUT0 + c] = W2[i];
    }
}

// ---------------- build CSR from dense binary graph (order-preserving) -------
__global__ void build_csr_kernel(const float* __restrict__ graph) {
    int row  = blockIdx.x * (blockDim.x >> 5) + (threadIdx.x >> 5);
    int lane = threadIdx.x & 31;
    if (row >= NNODES) return;
    const float* g = graph + (size_t)row * NNODES;
    int cnt = 0;
    for (int base = 0; base < NNODES; base += 32) {
        float v = g[base + lane];
        unsigned ball = __ballot_sync(0xffffffffu, v != 0.0f);
        int prefix = __popc(ball & ((1u << lane) - 1u));
        if (v != 0.0f) {
            int pos = cnt + prefix;
            if (pos < CAP) d_col[row * CAP + pos] = base + lane;
        }
        cnt += __popc(ball);
    }
    if (lane == 0) d_deg[row] = (cnt < CAP) ? cnt : CAP;
}

// ---------------- linear body: out[r][c] = sum_k x[r][k] * Wt[k][c] ----------
template <int DIN, int DOUT>
__device__ __forceinline__ void lin_body(const float* __restrict__ x,
                                         const float* __restrict__ wt,
                                         float* __restrict__ out) {
    constexpr int RPB = 32;
    __shared__ float xs[RPB * DIN];
    long base = (long)blockIdx.x * RPB;
    const float4* xg  = (const float4*)(x + base * DIN);
    float4*       xs4 = (float4*)xs;
    for (int i = threadIdx.x; i < RPB * DIN / 4; i += blockDim.x) xs4[i] = xg[i];
    __syncthreads();

    int c = threadIdx.x;   // blockDim == DOUT
    float acc[RPB];
#pragma unroll
    for (int r = 0; r < RPB; r++) acc[r] = 0.0f;

    for (int k = 0; k < DIN; k += 4) {
        float w0 = wt[(k + 0) * DOUT + c];
        float w1 = wt[(k + 1) * DOUT + c];
        float w2 = wt[(k + 2) * DOUT + c];
        float w3 = wt[(k + 3) * DOUT + c];
#pragma unroll
        for (int r = 0; r < RPB; r++) {
            float4 xv = *(const float4*)&xs[r * DIN + k];
            acc[r] = fmaf(xv.x, w0, fmaf(xv.y, w1, fmaf(xv.z, w2, fmaf(xv.w, w3, acc[r]))));
        }
    }
#pragma unroll
    for (int r = 0; r < RPB; r++) out[(base + r) * DOUT + c] = acc[r];
}

__global__ void lin1_kernel(const float* __restrict__ x) {
    lin_body<DIN0, DHID>(x, d_wt1, d_h1);
}
__global__ void lin2_kernel() {
    lin_body<DHID, DOUT0>(d_t1, d_wt2, d_h1);   // h2 aliases d_h1
}

// ---------------- sparse GAT aggregation: warp per (b, n) row ----------------
// out[b,n,:] = softmax_m( h[b,n]·h[b,m] over CSR neighbors ) @ h[b,m] + bias
// 4-neighbor batched online softmax: independent loads/dots give 4x ILP, one
// merged 10-SHFL reduction per 4 neighbors, serial (M,Z,acc) update per batch.
template <int D, bool RELU>
__device__ __forceinline__ void agg_body(const float* __restrict__ h,
                                         const float* __restrict__ bias,
                                         float* __restrict__ out) {
    constexpr int VEC = D / 32;
    int warp = threadIdx.x >> 5;
    int lane = threadIdx.x & 31;
    long row = (long)blockIdx.x * (blockDim.x >> 5) + warp;   // row in [0, B*N)
    if (row >= (long)BATCH * NNODES) return;
    int n = (int)(row & (NNODES - 1));
    const float* hb = h + (size_t)(row - n) * D;   // batch base

    float f[VEC];
    if (VEC == 4) {
        float4 t = *(const float4*)(hb + (size_t)n * D + lane * 4);
        f[0] = t.x; f[1] = t.y; f[2] = t.z; f[3] = t.w;
    } else {
        float2 t = *(const float2*)(hb + (size_t)n * D + lane * 2);
        f[0] = t.x; f[1] = t.y;
    }

    float M = -INFINITY, Z = 0.0f;
    float acc[VEC];
#pragma unroll
    for (int v = 0; v < VEC; v++) acc[v] = 0.0f;

    int deg = d_deg[n];
    const int* cols = d_col + (size_t)n * CAP;   // 2KB-aligned row base

    int i = 0;
    // ---- batched main loop: 4 neighbors per iteration ----
    for (; i + 4 <= deg; i += 4) {
        int4 mm = *(const int4*)(cols + i);      // aligned: base 512-int aligned, i%4==0
        float g0[VEC], g1[VEC], g2[VEC], g3[VEC];
        if (VEC == 4) {
            float4 t0 = *(const float4*)(hb + (size_t)mm.x * D + lane * 4);
            float4 t1 = *(const float4*)(hb + (size_t)mm.y * D + lane * 4);
            float4 t2 = *(const float4*)(hb + (size_t)mm.z * D + lane * 4);
            float4 t3 = *(const float4*)(hb + (size_t)mm.w * D + lane * 4);
            g0[0]=t0.x; g0[1]=t0.y; g0[2]=t0.z; g0[3]=t0.w;
            g1[0]=t1.x; g1[1]=t1.y; g1[2]=t1.z; g1[3]=t1.w;
            g2[0]=t2.x; g2[1]=t2.y; g2[2]=t2.z; g2[3]=t2.w;
            g3[0]=t3.x; g3[1]=t3.y; g3[2]=t3.z; g3[3]=t3.w;
        } else {
            float2 t0 = *(const float2*)(hb + (size_t)mm.x * D + lane * 2);
            float2 t1 = *(const float2*)(hb + (size_t)mm.y * D + lane * 2);
            float2 t2 = *(const float2*)(hb + (size_t)mm.z * D + lane * 2);
            float2 t3 = *(const float2*)(hb + (size_t)mm.w * D + lane * 2);
            g0[0]=t0.x; g0[1]=t0.y;  g1[0]=t1.x; g1[1]=t1.y;
            g2[0]=t2.x; g2[1]=t2.y;  g3[0]=t3.x; g3[1]=t3.y;
        }
        float p0 = 0.f, p1 = 0.f, p2 = 0.f, p3 = 0.f;
#pragma unroll
        for (int v = 0; v < VEC; v++) {
            p0 = fmaf(f[v], g0[v], p0);
            p1 = fmaf(f[v], g1[v], p1);
            p2 = fmaf(f[v], g2[v], p2);
            p3 = fmaf(f[v], g3[v], p3);
        }
        float d0, d1, d2, d3;
        warp_sum4(p0, p1, p2, p3, d0, d1, d2, d3);

        float bm   = fmaxf(fmaxf(d0, d1), fmaxf(d2, d3));
        float newM = fmaxf(M, bm);
        float sc   = __expf(M - newM);          // first batch: exp(-inf)=0
        float w0   = __expf(d0 - newM);
        float w1   = __expf(d1 - newM);
        float w2   = __expf(d2 - newM);
        float w3   = __expf(d3 - newM);
        Z = fmaf(Z, sc, (w0 + w1) + (w2 + w3));
#pragma unroll
        for (int v = 0; v < VEC; v++) {
            float a = acc[v] * sc;
            a = fmaf(w0, g0[v], a);
            a = fmaf(w1, g1[v], a);
            a = fmaf(w2, g2[v], a);
            a = fmaf(w3, g3[v], a);
            acc[v] = a;
        }
        M = newM;
    }
    // ---- tail ----
    for (; i < deg; i++) {
        int m = cols[i];
        float g[VEC];
        if (VEC == 4) {
            float4 t = *(const float4*)(hb + (size_t)m * D + lane * 4);
            g[0]=t.x; g[1]=t.y; g[2]=t.z; g[3]=t.w;
        } else {
            float2 t = *(const float2*)(hb + (size_t)m * D + lane * 2);
            g[0]=t.x; g[1]=t.y;
        }
        float p = 0.f;
#pragma unroll
        for (int v = 0; v < VEC; v++) p = fmaf(f[v], g[v], p);
        float dot = warp_sum(p);

        float newM = fmaxf(M, dot);
        float sc = __expf(M - newM);
        float w  = __expf(dot - newM);
        Z = fmaf(Z, sc, w);
#pragma unroll
        for (int v = 0; v < VEC; v++) acc[v] = fmaf(w, g[v], acc[v] * sc);
        M = newM;
    }

    float inv = 1.0f / fmaxf(Z, 1e-30f);   // deg>=1 via self-loop; guard anyway
    float* op = out + (size_t)row * D + lane * VEC;
#pragma unroll
    for (int v = 0; v < VEC; v++) {
        float o = fmaf(acc[v], inv, bias[lane * VEC + v]);
        if (RELU) o = fmaxf(o, 0.0f);
        op[v] = o;
    }
}

__global__ void agg1_kernel(const float* __restrict__ b1) {
    agg_body<DHID, true>(d_h1, b1, d_t1);
}
__global__ void agg2_kernel(const float* __restrict__ b2, float* __restrict__ out) {
    agg_body<DOUT0, false>(d_h1, b2, out);      // h2 aliases d_h1
}

// ---------------- launch ------------------------------------------------------
extern "C" void kernel_launch(void* const* d_in, const int* in_sizes, int n_in,
                              void* d_out, int out_size) {
    const float* flow_x = (const float*)d_in[0];   // [B,N,64]
    const float* graph  = (const float*)d_in[1];   // [N,N]
    const float* W1     = (const float*)d_in[2];   // [128,64]
    const float* b1     = (const float*)d_in[3];   // [128]
    const float* W2     = (const float*)d_in[4];   // [64,128]
    const float* b2     = (const float*)d_in[5];   // [64]
    float*       outp   = (float*)d_out;           // [B,N,1,64]

    // 1) transpose weights
    prep_kernel<<<(DHID * DIN0 + 255) / 256, 256>>>(W1, W2);
    // 2) build CSR (shared by both layers & all batches)
    build_csr_kernel<<<NNODES / 8, 256>>>(graph);
    // 3) layer-1 linear: h1 = x @ W1^T
    lin1_kernel<<<BATCH * NNODES / 32, DHID>>>(flow_x);
    // 4) layer-1 sparse attention + bias + relu
    agg1_kernel<<<(BATCH * NNODES) / 8, 256>>>(b1);
    // 5) layer-2 linear: h2 = t1 @ W2^T  (h2 aliases d_h1)
    lin2_kernel<<<BATCH * NNODES / 32, DOUT0>>>();
    // 6) layer-2 sparse attention + bias -> final output
    agg2_kernel<<<(BATCH * NNODES) / 8, 256>>>(b2, outp);
}